// round 15
// baseline (speedup 1.0000x reference)
#include <cuda_runtime.h>
#include <cuda_fp16.h>
#include <cuda_bf16.h>
#include <cstdint>

// BatchRankingLoss: G=511 groups of d=256 decoys.
// loss = sum_{g,i,j} w_ij * max(0, 1 + y_ij*(o_i - o_j)) / (G*d*(d-1))
//   y_ij = -1 if (t_i - t_j) < 0 else +1 ;  w_ij = |t_i - t_j| > 0.1
//
// Symmetry: term(i,j)==term(j,i) -> sum = 2 * sum over unordered pairs.
// Per row i: m=1..127 full weight, m=128 half weight.
//
// R13 conclusion: fp32 path bottomed out at ~11 SASS instr/term (issue ~54%,
// no pipe >29%). This round exploits the 1e-3 tolerance: the hot loop runs in
// PACKED fp16 (2 terms/instr on the fma pipe):
//   per 2 terms: HSUB2 dt, HSUB2 dd, LOP3 sign-apply (bitwise covers both
//   halves), LOP3 abs, __hfma2_relu (fuses 1+s with ReLU), __hgt2 0/1 gate,
//   __hfma2 masked accumulate  = 7 instr / 2 terms. LDS.32 loads one half2
//   column pair. fp16 accumulators (<=16 terms each) -> fp32 at the end.
// Gate error: fp16 rounding shifts |dt|>0.1 by <=1 ulp (~5e-5) -> ~1e-3 of
// pairs flip with random sign -> net rel err ~1e-5, well under 1e-3.
// Edge terms (prologue s=1..3, epilogue s=128..131 incl. m=128 half weight)
// stay exact fp32 via parallel fp32 smem arrays (~10 terms/thread).
//
// Structure (unchanged): CTA = 256 thr = ONE group; u=tid&63 -> 4-row block
// (rows 4u..4u+3); h=tid>>6 -> compile-time column slice as a partially
// unrolled loop (hot in L0 I$). Rows padded to 384 (first 128 duplicated) so
// r+s (s<=131) never wraps. Fused last-CTA (ticket) reduction writes d_out,
// resets ticket -> graph-replay deterministic.

#define D      256
#define PADR   384
#define THRESH 0.1f

__device__ float    g_group_sums[4096];
__device__ unsigned g_ticket;   // zero-init; reset by last CTA each call

__device__ __forceinline__ uint32_t h2u(__half2 h)
{
    return *reinterpret_cast<uint32_t*>(&h);
}
__device__ __forceinline__ __half2 u2h(uint32_t u)
{
    return *reinterpret_cast<__half2*>(&u);
}

// exact fp32 edge term: tj/oj from fp32 smem
__device__ __forceinline__ void acc_f32(float& acc, float oi, float ti,
                                        float tj, float oj)
{
    const float dt = ti - tj;
    const float dd = oi - oj;
    const uint32_t s =
        __float_as_uint(dd) ^ (__float_as_uint(dt) & 0x80000000u);
    const float q = fmaxf(0.0f, 1.0f + __uint_as_float(s));
    if (fabsf(dt) > THRESH) acc += q;
}

// One slice: NP half2 column-pairs starting at compile-time even offset S0.
template <int S0, int NP, int UNR>
__device__ __forceinline__ void do_slice(const __half* tb, const __half* ob,
                                         const __half2* ti2, const __half2* oi2,
                                         __half2* acc2)
{
    const __half2 one2 = __float2half2_rn(1.0f);
    const __half2 th2  = __float2half2_rn(THRESH);
#pragma unroll (UNR)
    for (int p = 0; p < NP; ++p) {
        const __half2 tj2 =
            *reinterpret_cast<const __half2*>(tb + S0 + 2 * p);   // LDS.32
        const __half2 oj2 =
            *reinterpret_cast<const __half2*>(ob + S0 + 2 * p);
#pragma unroll
        for (int k = 0; k < 4; ++k) {
            const __half2 dt2 = __hsub2(ti2[k], tj2);
            const __half2 dd2 = __hsub2(oi2[k], oj2);
            const uint32_t dtu = h2u(dt2);
            // sign-apply: one LOP3 (dd ^ (dt & signmask)), both halves
            const __half2 s2  = u2h(h2u(dd2) ^ (dtu & 0x80008000u));
            const __half2 ad2 = u2h(dtu & 0x7FFF7FFFu);            // |dt|
            const __half2 q2  = __hfma2_relu(s2, one2, one2);      // max(0,1+s)
            const __half2 w2  = __hgt2(ad2, th2);                  // 1.0 / 0.0
            acc2[k] = __hfma2(w2, q2, acc2[k]);
        }
    }
}

__global__ __launch_bounds__(256) void ranking_loss_kernel(
    const float* __restrict__ o_in,   // [B,1] -> [B]
    const float* __restrict__ t_in,   // [B]
    float* __restrict__ out,
    int G)
{
    __shared__ __align__(4) __half th_s[PADR];   // fp16 t
    __shared__ __align__(4) __half oh_s[PADR];   // fp16 o
    __shared__ float tf_s[PADR];                 // fp32 t (edges)
    __shared__ float of_s[PADR];                 // fp32 o (edges)
    __shared__ float wsum[8];
    __shared__ bool  is_last;

    const int tid = threadIdx.x;
    const int u   = tid & 63;          // 4-row block index
    const int h   = tid >> 6;          // column slice (warp-uniform)
    const int g   = blockIdx.x;
    const int r   = 4 * u;

    const float4 o4 = reinterpret_cast<const float4*>(o_in)[g * 64 + u];
    const float4 t4 = reinterpret_cast<const float4*>(t_in)[g * 64 + u];
    const float of[4] = {o4.x, o4.y, o4.z, o4.w};
    const float tf[4] = {t4.x, t4.y, t4.z, t4.w};

    if (h == 0) {                      // one writer per 4-row block
#pragma unroll
        for (int k = 0; k < 4; ++k) {
            th_s[r + k] = __float2half(tf[k]);
            oh_s[r + k] = __float2half(of[k]);
            tf_s[r + k] = tf[k];
            of_s[r + k] = of[k];
            if (r < 128) {             // duplicate first 128 rows -> no wrap
                th_s[D + r + k] = __float2half(tf[k]);
                oh_s[D + r + k] = __float2half(of[k]);
                tf_s[D + r + k] = tf[k];
                of_s[D + r + k] = of[k];
            }
        }
    }
    __syncthreads();

    const __half* tb = th_s + r;       // tb[s] = t[row r+s] (fp16)
    const __half* ob = oh_s + r;
    const float*  tF = tf_s + r;       // fp32 for edge terms
    const float*  oF = of_s + r;

    __half2 ti2[4], oi2[4];
#pragma unroll
    for (int k = 0; k < 4; ++k) {
        ti2[k] = __half2half2(__float2half(tf[k]));
        oi2[k] = __half2half2(__float2half(of[k]));
    }

    __half2 acc2[4] = {__float2half2_rn(0.f), __float2half2_rn(0.f),
                       __float2half2_rn(0.f), __float2half2_rn(0.f)};
    float accE = 0.f;                  // fp32 edge accumulator
    float ah   = 0.f;                  // m=128 half-weight accumulator (fp32)

    switch (h) {
    case 0:
        do_slice<4, 15, 5>(tb, ob, ti2, oi2, acc2);
        // prologue: s=1..3 (only rows with m = s-k >= 1), exact fp32
        acc_f32(accE, of[0], tf[0], tF[1], oF[1]);
        acc_f32(accE, of[0], tf[0], tF[2], oF[2]);
        acc_f32(accE, of[1], tf[1], tF[2], oF[2]);
        acc_f32(accE, of[0], tf[0], tF[3], oF[3]);
        acc_f32(accE, of[1], tf[1], tF[3], oF[3]);
        acc_f32(accE, of[2], tf[2], tF[3], oF[3]);
        break;
    case 1:
        do_slice<34, 16, 4>(tb, ob, ti2, oi2, acc2);
        break;
    case 2:
        do_slice<66, 16, 4>(tb, ob, ti2, oi2, acc2);
        break;
    default:
        do_slice<98, 15, 5>(tb, ob, ti2, oi2, acc2);
        // epilogue: s=128..131 ; m==128 terms -> half-weight acc, exact fp32
        acc_f32(ah,   of[0], tf[0], tF[128], oF[128]);   // m=128
        acc_f32(accE, of[1], tf[1], tF[128], oF[128]);   // m=127
        acc_f32(accE, of[2], tf[2], tF[128], oF[128]);   // m=126
        acc_f32(accE, of[3], tf[3], tF[128], oF[128]);   // m=125
        acc_f32(ah,   of[1], tf[1], tF[129], oF[129]);   // m=128
        acc_f32(accE, of[2], tf[2], tF[129], oF[129]);
        acc_f32(accE, of[3], tf[3], tF[129], oF[129]);
        acc_f32(ah,   of[2], tf[2], tF[130], oF[130]);   // m=128
        acc_f32(accE, of[3], tf[3], tF[130], oF[130]);
        acc_f32(ah,   of[3], tf[3], tF[131], oF[131]);   // m=128
        break;
    }

    // fp16 accumulators -> fp32
    float acc = accE + 0.5f * ah;
#pragma unroll
    for (int k = 0; k < 4; ++k) {
        const float2 f = __half22float2(acc2[k]);
        acc += f.x + f.y;
    }

    // CTA reduce (8 warps)
#pragma unroll
    for (int off = 16; off > 0; off >>= 1)
        acc += __shfl_xor_sync(0xffffffffu, acc, off);
    if ((tid & 31) == 0) wsum[tid >> 5] = acc;
    __syncthreads();

    if (tid == 0) {
        float s = 0.f;
#pragma unroll
        for (int w = 0; w < 8; ++w) s += wsum[w];
        g_group_sums[g] = s;
        __threadfence();
        unsigned old = atomicAdd(&g_ticket, 1u);
        is_last = (old == (unsigned)(G - 1));
    }
    __syncthreads();

    if (is_last) {
        __threadfence();                    // acquire other CTAs' sums
        float v = (tid < G) ? g_group_sums[tid] : 0.f;
        if (tid + 256 < G) v += g_group_sums[tid + 256];

#pragma unroll
        for (int off = 16; off > 0; off >>= 1)
            v += __shfl_xor_sync(0xffffffffu, v, off);
        if ((tid & 31) == 0) wsum[tid >> 5] = v;
        __syncthreads();

        if (tid == 0) {
            float s = 0.f;
#pragma unroll
            for (int w = 0; w < 8; ++w) s += wsum[w];
            const float inv_n = 1.0f / ((float)G * (float)D * (float)(D - 1));
            out[0] = 2.0f * s * inv_n;      // x2: unordered -> ordered pairs
            g_ticket = 0;                   // reset for next graph replay
        }
    }
}

extern "C" void kernel_launch(void* const* d_in, const int* in_sizes, int n_in,
                              void* d_out, int out_size)
{
    const float* o = (const float*)d_in[0];  // input  [B,1] f32
    const float* t = (const float*)d_in[1];  // gdt_ts [B]   f32
    float* out = (float*)d_out;

    const int B = in_sizes[1];
    const int K = B / D;            // 512
    const int G = K - 1;            // 511 (reference skips final group)

    ranking_loss_kernel<<<G, 256>>>(o, t, out, G);
}

// round 16
// speedup vs baseline: 1.0444x; 1.0444x over previous
#include <cuda_runtime.h>
#include <cuda_bf16.h>
#include <cstdint>

// BatchRankingLoss: G=511 groups of d=256 decoys.
// loss = sum_{g,i,j} w_ij * max(0, 1 + y_ij*(o_i - o_j)) / (G*d*(d-1))
//   y_ij = -1 if (t_i - t_j) < 0 else +1 ;  w_ij = |t_i - t_j| > 0.1
//
// Symmetry: term(i,j)==term(j,i) -> sum = 2 * sum over unordered pairs.
// Per row i: m=1..127 full weight, m=128 half weight (distance-128 pairs are
// generated by both endpoints).
//
// R15 conclusion: the "packed f32x2" path was an illusion — PTX add.rn.f32x2
// has no FADD2 in sm_103a SASS (only FFMA2 exists, per SASS_QUICKREF); ptxas
// split it and added pack/unpack MOVs, inflating every round since R8 to
// ~5.6M warp-instrs. This round is PURE SCALAR fp32: 7 SASS ops per term
// (FADD dt, FADD dd, LOP3 sign-apply, FADD 1+s, FMNMX relu, FSETP |dt|>th,
// @p FADD acc), LDS.64 of an (o,t) float2 amortized over 4 rows ->
// ~3.9M warp-instrs total, no asm at all.
//
// Structure (= R12, best issue): CTA = 256 thr = ONE group; u=tid&63 -> 4-row
// block (rows 4u..4u+3 in regs); h=tid>>6 -> compile-time column slice as a
// partially-unrolled loop (body hot in L0 I$); single smem float2 base with
// immediate offsets. s = column offset from block base; row k sees m = s-k:
//   h=0: s=4..34   (31 cols) + prologue s=1..3
//   h=1: s=35..65  (31)
//   h=2: s=66..96  (31)
//   h=3: s=97..127 (31) + epilogue s=128..131 (m=128 -> half weight)
// Rows padded to 384 (first 128 duplicated) so r+s (s<=131) never wraps.
//
// Fused reduction: group sums -> scratch; last CTA (ticket) writes d_out and
// resets the ticket -> graph-replay deterministic.

#define D      256
#define PADR   384
#define THRESH 0.1f

__device__ float    g_group_sums[4096];
__device__ unsigned g_ticket;   // zero-init; reset by last CTA each call

// v = (o_j, t_j). 7 SASS ops; compiler if-converts the guard (R13 verified
// explicit predication is neutral -> plain C++).
__device__ __forceinline__ void acc_term(float& acc, float oi, float ti,
                                         float2 v)
{
    const float dt = ti - v.y;
    const float dd = oi - v.x;
    // y*do via sign-bit xor (y=-1 iff dt<0; dt==+-0 is weighted out)
    const uint32_t s =
        __float_as_uint(dd) ^ (__float_as_uint(dt) & 0x80000000u);
    const float q = fmaxf(0.0f, 1.0f + __uint_as_float(s));
    if (fabsf(dt) > THRESH) acc += q;
}

// One slice: NC columns starting at compile-time S0, partially unrolled so
// the body stays resident in L0 I$ while LDS stays [Rbase+imm].
template <int S0, int NC, int UNR>
__device__ __forceinline__ void do_slice(const float2* base,
                                         const float* oi, const float* ti,
                                         float* acc)
{
#pragma unroll (UNR)
    for (int s = S0; s < S0 + NC; ++s) {
        const float2 v = base[s];          // LDS.64
        acc_term(acc[0], oi[0], ti[0], v);
        acc_term(acc[1], oi[1], ti[1], v);
        acc_term(acc[2], oi[2], ti[2], v);
        acc_term(acc[3], oi[3], ti[3], v);
    }
}

__global__ __launch_bounds__(256) void ranking_loss_kernel(
    const float* __restrict__ o_in,   // [B,1] -> [B]
    const float* __restrict__ t_in,   // [B]
    float* __restrict__ out,
    int G)
{
    __shared__ __align__(16) float2 ot[PADR];   // (o, t) per row
    __shared__ float wsum[8];
    __shared__ bool  is_last;

    const int tid = threadIdx.x;
    const int u   = tid & 63;          // 4-row block index
    const int h   = tid >> 6;          // column slice (warp-uniform)
    const int g   = blockIdx.x;
    const int r   = 4 * u;

    const float4 o4 = reinterpret_cast<const float4*>(o_in)[g * 64 + u];
    const float4 t4 = reinterpret_cast<const float4*>(t_in)[g * 64 + u];
    const float oi[4] = {o4.x, o4.y, o4.z, o4.w};
    const float ti[4] = {t4.x, t4.y, t4.z, t4.w};

    if (h == 0) {                      // one writer per 4-row block
#pragma unroll
        for (int k = 0; k < 4; ++k) {
            ot[r + k] = make_float2(oi[k], ti[k]);
            if (r < 128)               // duplicate first 128 rows -> no wrap
                ot[D + r + k] = make_float2(oi[k], ti[k]);
        }
    }
    __syncthreads();

    const float2* base = ot + r;       // base[s] = (o,t) of row r+s

    float acc[4] = {0.f, 0.f, 0.f, 0.f};
    float ah     = 0.f;                // m=128 half-weight accumulator

    switch (h) {
    case 0:
        do_slice<4, 31, 4>(base, oi, ti, acc);
        // prologue: s=1..3 (only rows with m = s-k >= 1)
        acc_term(acc[0], oi[0], ti[0], base[1]);
        acc_term(acc[0], oi[0], ti[0], base[2]);
        acc_term(acc[1], oi[1], ti[1], base[2]);
        acc_term(acc[0], oi[0], ti[0], base[3]);
        acc_term(acc[1], oi[1], ti[1], base[3]);
        acc_term(acc[2], oi[2], ti[2], base[3]);
        break;
    case 1:
        do_slice<35, 31, 4>(base, oi, ti, acc);
        break;
    case 2:
        do_slice<66, 31, 4>(base, oi, ti, acc);
        break;
    default:
        do_slice<97, 31, 4>(base, oi, ti, acc);
        // epilogue: s=128..131 ; m==128 terms -> half-weight acc
        acc_term(ah,     oi[0], ti[0], base[128]);   // m=128
        acc_term(acc[1], oi[1], ti[1], base[128]);   // m=127
        acc_term(acc[2], oi[2], ti[2], base[128]);   // m=126
        acc_term(acc[3], oi[3], ti[3], base[128]);   // m=125
        acc_term(ah,     oi[1], ti[1], base[129]);   // m=128
        acc_term(acc[2], oi[2], ti[2], base[129]);
        acc_term(acc[3], oi[3], ti[3], base[129]);
        acc_term(ah,     oi[2], ti[2], base[130]);   // m=128
        acc_term(acc[3], oi[3], ti[3], base[130]);
        acc_term(ah,     oi[3], ti[3], base[131]);   // m=128
        break;
    }

    float a = ((acc[0] + acc[1]) + (acc[2] + acc[3])) + 0.5f * ah;

    // CTA reduce (8 warps)
#pragma unroll
    for (int off = 16; off > 0; off >>= 1)
        a += __shfl_xor_sync(0xffffffffu, a, off);
    if ((tid & 31) == 0) wsum[tid >> 5] = a;
    __syncthreads();

    if (tid == 0) {
        float s = 0.f;
#pragma unroll
        for (int w = 0; w < 8; ++w) s += wsum[w];
        g_group_sums[g] = s;
        __threadfence();
        unsigned old = atomicAdd(&g_ticket, 1u);
        is_last = (old == (unsigned)(G - 1));
    }
    __syncthreads();

    if (is_last) {
        __threadfence();                    // acquire other CTAs' sums
        float v = (tid < G) ? g_group_sums[tid] : 0.f;
        if (tid + 256 < G) v += g_group_sums[tid + 256];

#pragma unroll
        for (int off = 16; off > 0; off >>= 1)
            v += __shfl_xor_sync(0xffffffffu, v, off);
        if ((tid & 31) == 0) wsum[tid >> 5] = v;
        __syncthreads();

        if (tid == 0) {
            float s = 0.f;
#pragma unroll
            for (int w = 0; w < 8; ++w) s += wsum[w];
            const float inv_n = 1.0f / ((float)G * (float)D * (float)(D - 1));
            out[0] = 2.0f * s * inv_n;      // x2: unordered -> ordered pairs
            g_ticket = 0;                   // reset for next graph replay
        }
    }
}

extern "C" void kernel_launch(void* const* d_in, const int* in_sizes, int n_in,
                              void* d_out, int out_size)
{
    const float* o = (const float*)d_in[0];  // input  [B,1] f32
    const float* t = (const float*)d_in[1];  // gdt_ts [B]   f32
    float* out = (float*)d_out;

    const int B = in_sizes[1];
    const int K = B / D;            // 512
    const int G = K - 1;            // 511 (reference skips final group)

    ranking_loss_kernel<<<G, 256>>>(o, t, out, G);
}